// round 16
// baseline (speedup 1.0000x reference)
#include <cuda_runtime.h>
#include <math.h>

// Problem shape (fixed by dataset)
#define BB   16
#define NN   1024
#define DD   64
#define CC   64
#define KMAX 20
#define KB   20     // edgeconv neighbor blocking: single pass
#define RPW  4      // knn rows per warp
#define ROWS 32     // knn rows per block (8 warps * RPW)

#define F_INF __int_as_float(0x7f800000)

typedef unsigned long long u64;

// ---- f32x2 packed helpers (sm_100+ PTX): fma2(a,b,c) = a*b + c ----
static __device__ __forceinline__ u64 fma2(u64 a, u64 b, u64 c) {
    u64 d;
    asm("fma.rn.f32x2 %0, %1, %2, %3;" : "=l"(d) : "l"(a), "l"(b), "l"(c));
    return d;
}
static __device__ __forceinline__ u64 pack2(float lo, float hi) {
    u64 r;
    asm("mov.b64 %0, {%1, %2};" : "=l"(r)
        : "r"(__float_as_uint(lo)), "r"(__float_as_uint(hi)));
    return r;
}
static __device__ __forceinline__ void unpack2(u64 v, float& lo, float& hi) {
    unsigned int a, b;
    asm("mov.b64 {%0, %1}, %2;" : "=r"(a), "=r"(b) : "l"(v));
    lo = __uint_as_float(a); hi = __uint_as_float(b);
}

// ---------------- scratch (no allocations allowed) ----------------
__device__ int   g_idx[BB * NN * KMAX];
__device__ float g_x2[BB * NN];      // +inf for masked-out points
__device__ int   g_counts[BB];
__device__ int   g_fv[BB];
__device__ int   g_keff[BB];
__device__ int   g_kglobal[1];

// ---------------- kernel A: norms (masked -> +inf) + per-batch stats ----------------
__global__ void prep_kernel(const float* __restrict__ x,
                            const int* __restrict__ mask) {
    int b = blockIdx.x;
    int tid = threadIdx.x;

    for (int i = tid; i < NN; i += 256) {
        const float4* row = reinterpret_cast<const float4*>(x + ((size_t)b * NN + i) * DD);
        float s = 0.f;
#pragma unroll
        for (int q = 0; q < DD / 4; q++) {
            float4 v = row[q];
            s += v.x * v.x + v.y * v.y + v.z * v.z + v.w * v.w;
        }
        g_x2[b * NN + i] = (mask[b * NN + i] != 0) ? s : F_INF;
    }

    int cnt = 0, fv = 1 << 30;
    for (int i = tid; i < NN; i += 256) {
        if (mask[b * NN + i] != 0) { cnt++; if (i < fv) fv = i; }
    }
    __shared__ int sc[256], sf[256];
    sc[tid] = cnt; sf[tid] = fv;
    __syncthreads();
    for (int s = 128; s > 0; s >>= 1) {
        if (tid < s) { sc[tid] += sc[tid + s]; sf[tid] = min(sf[tid], sf[tid + s]); }
        __syncthreads();
    }
    if (tid == 0) {
        g_counts[b] = sc[0];
        g_fv[b] = (sf[0] == (1 << 30)) ? 0 : sf[0];
    }
}

// ---------------- kernel A2: k_eff / k_global ----------------
__global__ void finalize_kernel() {
    __shared__ int mn;
    if (threadIdx.x == 0) {
        int m = g_counts[0];
        for (int i = 1; i < BB; i++) m = min(m, g_counts[i]);
        mn = m;
    }
    __syncthreads();
    int kg = min(KMAX, max(1, mn - 1));
    if (threadIdx.x == 0) g_kglobal[0] = kg;
    if (threadIdx.x < BB) {
        int b = threadIdx.x;
        float kp = sqrtf((float)g_counts[b] / 50.0f) * 8.0f;
        kp = fminf(fmaxf(kp, 8.0f), 20.0f);
        int ke = min((int)kp, kg);   // truncation matches .astype(int32)
        g_keff[b] = ke;
    }
}

// ---------------- kernel B: masked KNN (32 rows / block, 4 rows / warp) ----------------
// smem: dist[32][1024] + xjT[64][66] + xi_dup[32][64] (f32x2)
#define KNN_SMEM ((ROWS * NN + 64 * 66 + ROWS * 64 * 2) * 4)

// scan this lane's stripe (pairs p = t*32+lane): ascending j, strict <
// keeps the smallest index on ties (matches stable lax.top_k).
static __device__ __forceinline__ void scan_stripe(const float2* __restrict__ dp,
                                                   int lane, float& bv, int& bj) {
    bv = F_INF; bj = 0x7fffffff;
#pragma unroll 4
    for (int t = 0; t < NN / 64; t++) {
        int p = t * 32 + lane;
        float2 v = dp[p];
        int j0 = p * 2;
        if (v.x < bv) { bv = v.x; bj = j0; }
        if (v.y < bv) { bv = v.y; bj = j0 + 1; }
    }
}

__global__ void __launch_bounds__(256, 1)
knn_kernel(const float* __restrict__ x, const int* __restrict__ mask) {
    extern __shared__ float sm[];
    float* dist_s = sm;                      // 32*1024
    float* xjT    = sm + ROWS * NN;          // 64*66 (d-major, 8B rows)
    float* xid    = xjT + 64 * 66;           // 32*64 duplicated pairs

    const int w = threadIdx.x >> 5;
    const int lane = threadIdx.x & 31;
    const int b = blockIdx.y;
    const int i0 = blockIdx.x * ROWS;

    // load xi rows (32), duplicated for f32x2 broadcast
    for (int e = threadIdx.x; e < ROWS * DD; e += 256) {
        float v = x[((size_t)b * NN + i0) * DD + e];
        xid[e * 2] = v; xid[e * 2 + 1] = v;
    }
    __syncthreads();

    int   ir[RPW];
    float x2r[RPW];
    bool  mk[RPW];
    const u64* xp[RPW];
    bool any = false;
#pragma unroll
    for (int r = 0; r < RPW; r++) {
        ir[r] = i0 + w + 8 * r;
        x2r[r] = g_x2[b * NN + ir[r]];
        mk[r] = mask[b * NN + ir[r]] != 0;
        any |= mk[r];
        xp[r] = (const u64*)(xid) + (size_t)(w + 8 * r) * DD;
    }

    for (int jt = 0; jt < NN / 64; jt++) {
        const int j0base = jt * 64;
        __syncthreads();  // protect previous tile readers
        for (int e = threadIdx.x; e < 64 * DD; e += 256) {
            int r = e >> 6, d = e & 63;
            xjT[d * 66 + r] = x[((size_t)b * NN + j0base + r) * DD + d];
        }
        __syncthreads();

        if (any) {
            u64 acc[RPW];
#pragma unroll
            for (int r = 0; r < RPW; r++) acc[r] = 0;
#pragma unroll
            for (int d = 0; d < DD; d++) {
                u64 xjv = *(const u64*)(xjT + d * 66 + 2 * lane);
#pragma unroll
                for (int r = 0; r < RPW; r++)
                    acc[r] = fma2(xjv, xp[r][d], acc[r]);
            }
            int j0 = j0base + 2 * lane, j1 = j0 + 1;
            float2 x2j = *(const float2*)(g_x2 + (size_t)b * NN + j0);
#pragma unroll
            for (int r = 0; r < RPW; r++) {
                float a0, a1; unpack2(acc[r], a0, a1);
                float d0 = fmaxf(x2r[r] + x2j.x - 2.f * a0, 0.f);
                float d1 = fmaxf(x2r[r] + x2j.y - 2.f * a1, 0.f);
                if (j0 == ir[r]) d0 = F_INF;
                if (j1 == ir[r]) d1 = F_INF;
                if (mk[r])
                    *(float2*)(dist_s + (w + 8 * r) * NN + j0) = make_float2(d0, d1);
            }
        }
    }
    __syncwarp();

    const int keff = g_keff[b];
    const int kglob = g_kglobal[0];
    const int fv = g_fv[b];

    for (int r = 0; r < RPW; r++) {
        const int row = w + 8 * r;
        const int i = i0 + row;
        int* idxrow = g_idx + ((size_t)(b * NN + i)) * KMAX;

        if (!mk[r]) {
            for (int kk = lane; kk < KMAX; kk += 32) idxrow[kk] = 0;
            continue;
        }

        // tournament top-k: one full scan, then per-extraction warp
        // reduce + owner-only stripe rescan (smaller-index tie break)
        const float2* dp = (const float2*)(dist_s + row * NN);
        float bv; int bj;
        scan_stripe(dp, lane, bv, bj);       // cached per-lane local best

        for (int kk = 0; kk < keff; kk++) {
            float rv = bv; int rj = bj;
#pragma unroll
            for (int off = 16; off; off >>= 1) {
                float ov = __shfl_xor_sync(0xffffffffu, rv, off);
                int   oj = __shfl_xor_sync(0xffffffffu, rj, off);
                if (ov < rv || (ov == rv && oj < rj)) { rv = ov; rj = oj; }
            }
            if (rj >= NN) rj = 0;            // can't happen (count>=256); safety only
            if (lane == 0) idxrow[kk] = rj;
            // owner of pair (rj>>1): lane = pair % 32
            if (lane == ((rj >> 1) & 31)) {
                dist_s[row * NN + rj] = F_INF;   // remove, refresh my local best
                scan_stripe(dp, lane, bv, bj);
            }
        }
        for (int kk = keff + lane; kk < KMAX; kk += 32)
            idxrow[kk] = (kk < kglob) ? fv : 0;
    }
}

// ---------------- kernel C: edge MLP + GN + relu + MLP + max (f32x2, 20-nb single pass) ----------------
// smem: W1[128][64] + W2[64][64] + xi[8][64] + dup[8][KB][64] f32x2 + 4*64 params
#define EC_SMEM ((128 * 64 + 64 * 64 + 8 * 64 + 8 * KB * 64 * 2 + 4 * 64) * 4)

__global__ void __launch_bounds__(256, 1)
edgeconv_kernel(const float* __restrict__ x, const int* __restrict__ mask,
                const float* __restrict__ W1, const float* __restrict__ b1,
                const float* __restrict__ gamma, const float* __restrict__ beta,
                const float* __restrict__ W2, const float* __restrict__ b2,
                float* __restrict__ out) {
    extern __shared__ float sm[];
    float* W1s = sm;                             // 128*64
    float* W2s = W1s + 128 * 64;                 // 64*64
    float* xi_s = W2s + 64 * 64;                 // 8*64
    float* dup  = xi_s + 8 * 64;                 // 8 warps * KB * 64 f32x2
    float* b1s = dup + 8 * KB * 64 * 2;          // 64
    float* b2s = b1s + 64;
    float* gms = b2s + 64;
    float* bts = gms + 64;

    const int w = threadIdx.x >> 5;
    const int lane = threadIdx.x & 31;
    const int b = blockIdx.y;
    const int i0 = blockIdx.x * 8;
    const int i = i0 + w;
    const int c0 = 2 * lane;

    for (int e = threadIdx.x; e < 128 * 64; e += 256) W1s[e] = W1[e];
    for (int e = threadIdx.x; e < 64 * 64; e += 256) W2s[e] = W2[e];
    for (int e = threadIdx.x; e < 8 * 64; e += 256)
        xi_s[e] = x[((size_t)b * NN + i0) * DD + e];
    if (threadIdx.x < 64) {
        int t = threadIdx.x;
        b1s[t] = b1[t]; b2s[t] = b2[t]; gms[t] = gamma[t]; bts[t] = beta[t];
    }
    __syncthreads();

    const bool maski = mask[b * NN + i] != 0;
    float* orow = out + ((size_t)(b * NN + i)) * CC;
    if (!maski) {
        *(float2*)(orow + c0) = make_float2(0.f, 0.f);
        return;   // no block-wide barriers below (warp-local sync only)
    }

    // hoisted per-lane channel params (packed)
    const float2 gmv = *(const float2*)(gms + c0);
    const float2 btv = *(const float2*)(bts + c0);
    const u64 b2p = *(const u64*)(b2s + c0);

    // base = b1 + x_i @ W1[:64]  (identical for all k neighbors), packed {c0,c0+1}
    u64 basep = *(const u64*)(b1s + c0);
#pragma unroll 8
    for (int d = 0; d < DD; d++) {
        float e = xi_s[w * DD + d];
        u64 wv = *(const u64*)(W1s + d * CC + c0);
        basep = fma2(pack2(e, e), wv, basep);
    }

    float m0 = -F_INF, m1 = -F_INF;
    const int* idxrow = g_idx + ((size_t)(b * NN + i)) * KMAX;
    float* mydup = dup + w * KB * 64 * 2;            // KB neighbors x 64 f32x2
    const u64* mydupU = (const u64*)mydup;

    // ---- single pass over all 20 neighbors ----
    {
        // stage (x_nb - x_i), duplicated for f32x2 broadcast
#pragma unroll
        for (int u = 0; u < KB; u++) {
            int jn = idxrow[u];
            const float* xr = x + ((size_t)b * NN + jn) * DD;
            float e0 = xr[lane]      - xi_s[w * DD + lane];
            float e1 = xr[lane + 32] - xi_s[w * DD + lane + 32];
            ((float2*)mydup)[u * 64 + lane]      = make_float2(e0, e0);
            ((float2*)mydup)[u * 64 + lane + 32] = make_float2(e1, e1);
        }
        __syncwarp();

        u64 a[KB];
#pragma unroll
        for (int u = 0; u < KB; u++) a[u] = basep;

#pragma unroll 4
        for (int d = 0; d < DD; d++) {
            u64 wv = *(const u64*)(W1s + (DD + d) * CC + c0);
#pragma unroll
            for (int u = 0; u < KB; u++)
                a[u] = fma2(mydupU[u * 64 + d], wv, a[u]);
        }
        __syncwarp();  // dup reads done; buffer reused for h

        // GroupNorm(16 groups of 4 ch) + relu. Lane owns ch {2L,2L+1};
        // partner lane L^1 owns the other half of the 4-ch group.
#pragma unroll
        for (int u = 0; u < KB; u++) {
            float v0, v1; unpack2(a[u], v0, v1);
            float s = v0 + v1;
            s += __shfl_xor_sync(0xffffffffu, s, 1);
            float mu = s * 0.25f;
            float dv0 = v0 - mu, dv1 = v1 - mu;
            float q = dv0 * dv0 + dv1 * dv1;
            q += __shfl_xor_sync(0xffffffffu, q, 1);
            float rs = rsqrtf(q * 0.25f + 1e-5f);
            float h0 = fmaxf(dv0 * rs * gmv.x + btv.x, 0.f);
            float h1 = fmaxf(dv1 * rs * gmv.y + btv.y, 0.f);
            // duplicated store: dup[u][c0]={h0,h0}, dup[u][c0+1]={h1,h1}
            ((float4*)mydup)[(u * 64 + c0) >> 1] = make_float4(h0, h0, h1, h1);
        }
        __syncwarp();

        // h @ W2 + b2
        u64 o[KB];
#pragma unroll
        for (int u = 0; u < KB; u++) o[u] = b2p;
#pragma unroll 4
        for (int c = 0; c < CC; c++) {
            u64 wv = *(const u64*)(W2s + c * CC + c0);
#pragma unroll
            for (int u = 0; u < KB; u++)
                o[u] = fma2(mydupU[u * 64 + c], wv, o[u]);
        }
#pragma unroll
        for (int u = 0; u < KB; u++) {
            float v0, v1; unpack2(o[u], v0, v1);
            m0 = fmaxf(m0, v0);
            m1 = fmaxf(m1, v1);
        }
    }

    *(float2*)(orow + c0) = make_float2(m0, m1);
}

// ---------------- launch ----------------
extern "C" void kernel_launch(void* const* d_in, const int* in_sizes, int n_in,
                              void* d_out, int out_size) {
    const float* x      = (const float*)d_in[0];
    const int*   mask   = (const int*)d_in[1];
    const float* W1     = (const float*)d_in[2];
    const float* b1     = (const float*)d_in[3];
    const float* gamma  = (const float*)d_in[4];
    const float* beta   = (const float*)d_in[5];
    const float* W2     = (const float*)d_in[6];
    const float* b2     = (const float*)d_in[7];
    float* out          = (float*)d_out;

    cudaFuncSetAttribute(knn_kernel, cudaFuncAttributeMaxDynamicSharedMemorySize, KNN_SMEM);
    cudaFuncSetAttribute(edgeconv_kernel, cudaFuncAttributeMaxDynamicSharedMemorySize, EC_SMEM);
    (void)in_sizes; (void)n_in; (void)out_size;

    prep_kernel<<<BB, 256>>>(x, mask);
    finalize_kernel<<<1, 32>>>();
    knn_kernel<<<dim3(NN / ROWS, BB), 256, KNN_SMEM>>>(x, mask);
    edgeconv_kernel<<<dim3(NN / 8, BB), 256, EC_SMEM>>>(x, mask, W1, b1, gamma, beta, W2, b2, out);
}

// round 17
// speedup vs baseline: 1.1309x; 1.1309x over previous
#include <cuda_runtime.h>
#include <math.h>

// Problem shape (fixed by dataset)
#define BB   16
#define NN   1024
#define DD   64
#define CC   64
#define KMAX 20
#define KB   10     // edgeconv neighbor blocking (20 = 2 passes of 10)
#define RPW  2      // knn rows per warp
#define ROWS 16     // knn rows per block (8 warps * RPW)

#define F_INF __int_as_float(0x7f800000)

typedef unsigned long long u64;

// ---- f32x2 packed helpers (sm_100+ PTX): fma2(a,b,c) = a*b + c ----
static __device__ __forceinline__ u64 fma2(u64 a, u64 b, u64 c) {
    u64 d;
    asm("fma.rn.f32x2 %0, %1, %2, %3;" : "=l"(d) : "l"(a), "l"(b), "l"(c));
    return d;
}
static __device__ __forceinline__ u64 pack2(float lo, float hi) {
    u64 r;
    asm("mov.b64 %0, {%1, %2};" : "=l"(r)
        : "r"(__float_as_uint(lo)), "r"(__float_as_uint(hi)));
    return r;
}
static __device__ __forceinline__ void unpack2(u64 v, float& lo, float& hi) {
    unsigned int a, b;
    asm("mov.b64 {%0, %1}, %2;" : "=r"(a), "=r"(b) : "l"(v));
    lo = __uint_as_float(a); hi = __uint_as_float(b);
}

// ---------------- scratch (no allocations allowed) ----------------
__device__ int   g_idx[BB * NN * KMAX];
__device__ float g_x2[BB * NN];      // +inf for masked-out points
__device__ int   g_counts[BB];
__device__ int   g_fv[BB];
__device__ int   g_keff[BB];
__device__ int   g_kglobal[1];

// ---------------- kernel A: norms (masked -> +inf) + per-batch stats ----------------
__global__ void prep_kernel(const float* __restrict__ x,
                            const int* __restrict__ mask) {
    int b = blockIdx.x;
    int tid = threadIdx.x;

    for (int i = tid; i < NN; i += 256) {
        const float4* row = reinterpret_cast<const float4*>(x + ((size_t)b * NN + i) * DD);
        float s = 0.f;
#pragma unroll
        for (int q = 0; q < DD / 4; q++) {
            float4 v = row[q];
            s += v.x * v.x + v.y * v.y + v.z * v.z + v.w * v.w;
        }
        g_x2[b * NN + i] = (mask[b * NN + i] != 0) ? s : F_INF;
    }

    int cnt = 0, fv = 1 << 30;
    for (int i = tid; i < NN; i += 256) {
        if (mask[b * NN + i] != 0) { cnt++; if (i < fv) fv = i; }
    }
    __shared__ int sc[256], sf[256];
    sc[tid] = cnt; sf[tid] = fv;
    __syncthreads();
    for (int s = 128; s > 0; s >>= 1) {
        if (tid < s) { sc[tid] += sc[tid + s]; sf[tid] = min(sf[tid], sf[tid + s]); }
        __syncthreads();
    }
    if (tid == 0) {
        g_counts[b] = sc[0];
        g_fv[b] = (sf[0] == (1 << 30)) ? 0 : sf[0];
    }
}

// ---------------- kernel A2: k_eff / k_global ----------------
__global__ void finalize_kernel() {
    __shared__ int mn;
    if (threadIdx.x == 0) {
        int m = g_counts[0];
        for (int i = 1; i < BB; i++) m = min(m, g_counts[i]);
        mn = m;
    }
    __syncthreads();
    int kg = min(KMAX, max(1, mn - 1));
    if (threadIdx.x == 0) g_kglobal[0] = kg;
    if (threadIdx.x < BB) {
        int b = threadIdx.x;
        float kp = sqrtf((float)g_counts[b] / 50.0f) * 8.0f;
        kp = fminf(fmaxf(kp, 8.0f), 20.0f);
        int ke = min((int)kp, kg);   // truncation matches .astype(int32)
        g_keff[b] = ke;
    }
}

// ---------------- kernel B: masked KNN (16 rows / block, 2 rows / warp) ----------------
// smem: dist[16][1024] + xjT[64][66] + xi_dup[16][64] (f32x2)
#define KNN_SMEM ((ROWS * NN + 64 * 66 + ROWS * 64 * 2) * 4)

// scan this lane's stripe (pairs p = t*32+lane): ascending j, strict <
// keeps the smallest index on ties (matches stable lax.top_k).
static __device__ __forceinline__ void scan_stripe(const float2* __restrict__ dp,
                                                   int lane, float& bv, int& bj) {
    bv = F_INF; bj = 0x7fffffff;
#pragma unroll 4
    for (int t = 0; t < NN / 64; t++) {
        int p = t * 32 + lane;
        float2 v = dp[p];
        int j0 = p * 2;
        if (v.x < bv) { bv = v.x; bj = j0; }
        if (v.y < bv) { bv = v.y; bj = j0 + 1; }
    }
}

__global__ void __launch_bounds__(256, 2)
knn_kernel(const float* __restrict__ x, const int* __restrict__ mask) {
    extern __shared__ float sm[];
    float* dist_s = sm;                      // 16*1024
    float* xjT    = sm + ROWS * NN;          // 64*66 (d-major, 8B rows)
    float* xid    = xjT + 64 * 66;           // 16*64 duplicated pairs

    const int w = threadIdx.x >> 5;
    const int lane = threadIdx.x & 31;
    const int b = blockIdx.y;
    const int i0 = blockIdx.x * ROWS;

    // load xi rows (16), duplicated for f32x2 broadcast
    for (int e = threadIdx.x; e < ROWS * DD; e += 256) {
        float v = x[((size_t)b * NN + i0) * DD + e];
        xid[e * 2] = v; xid[e * 2 + 1] = v;
    }
    __syncthreads();

    const int iA = i0 + w, iB = i0 + w + 8;
    const float x2A = g_x2[b * NN + iA];
    const float x2B = g_x2[b * NN + iB];
    const bool maskA = mask[b * NN + iA] != 0;
    const bool maskB = mask[b * NN + iB] != 0;
    const bool any = maskA || maskB;
    const u64* xidA = (const u64*)(xid) + (size_t)w * DD;
    const u64* xidB = (const u64*)(xid) + (size_t)(w + 8) * DD;

    for (int jt = 0; jt < NN / 64; jt++) {
        const int j0base = jt * 64;
        __syncthreads();  // protect previous tile readers
        for (int e = threadIdx.x; e < 64 * DD; e += 256) {
            int r = e >> 6, d = e & 63;
            xjT[d * 66 + r] = x[((size_t)b * NN + j0base + r) * DD + d];
        }
        __syncthreads();

        if (any) {
            u64 accA = 0, accB = 0;
#pragma unroll
            for (int d = 0; d < DD; d++) {
                u64 xjv = *(const u64*)(xjT + d * 66 + 2 * lane);
                accA = fma2(xjv, xidA[d], accA);
                accB = fma2(xjv, xidB[d], accB);
            }
            int j0 = j0base + 2 * lane, j1 = j0 + 1;
            float2 x2j = *(const float2*)(g_x2 + (size_t)b * NN + j0);
            float a0, a1;
            unpack2(accA, a0, a1);
            {
                float d0 = fmaxf(x2A + x2j.x - 2.f * a0, 0.f);
                float d1 = fmaxf(x2A + x2j.y - 2.f * a1, 0.f);
                if (j0 == iA) d0 = F_INF;
                if (j1 == iA) d1 = F_INF;
                if (maskA) *(float2*)(dist_s + w * NN + j0) = make_float2(d0, d1);
            }
            unpack2(accB, a0, a1);
            {
                float d0 = fmaxf(x2B + x2j.x - 2.f * a0, 0.f);
                float d1 = fmaxf(x2B + x2j.y - 2.f * a1, 0.f);
                if (j0 == iB) d0 = F_INF;
                if (j1 == iB) d1 = F_INF;
                if (maskB) *(float2*)(dist_s + (w + 8) * NN + j0) = make_float2(d0, d1);
            }
        }
    }
    __syncwarp();

    const int keff = g_keff[b];
    const int kglob = g_kglobal[0];
    const int fv = g_fv[b];

    for (int r = 0; r < RPW; r++) {
        const int row = w + 8 * r;
        const int i = i0 + row;
        const bool maski = r ? maskB : maskA;
        int* idxrow = g_idx + ((size_t)(b * NN + i)) * KMAX;

        if (!maski) {
            for (int kk = lane; kk < KMAX; kk += 32) idxrow[kk] = 0;
            continue;
        }

        // tournament top-k: one full scan, then per-extraction warp
        // reduce + owner-only stripe rescan (smaller-index tie break)
        const float2* dp = (const float2*)(dist_s + row * NN);
        float bv; int bj;
        scan_stripe(dp, lane, bv, bj);       // cached per-lane local best

        for (int kk = 0; kk < keff; kk++) {
            float rv = bv; int rj = bj;
#pragma unroll
            for (int off = 16; off; off >>= 1) {
                float ov = __shfl_xor_sync(0xffffffffu, rv, off);
                int   oj = __shfl_xor_sync(0xffffffffu, rj, off);
                if (ov < rv || (ov == rv && oj < rj)) { rv = ov; rj = oj; }
            }
            if (rj >= NN) rj = 0;            // can't happen (count>=256); safety only
            if (lane == 0) idxrow[kk] = rj;
            // owner of pair (rj>>1): lane = pair % 32
            if (lane == ((rj >> 1) & 31)) {
                dist_s[row * NN + rj] = F_INF;   // remove, refresh my local best
                scan_stripe(dp, lane, bv, bj);
            }
        }
        for (int kk = keff + lane; kk < KMAX; kk += 32)
            idxrow[kk] = (kk < kglob) ? fv : 0;
    }
}

// ---------------- kernel C: edge MLP + GN + relu + MLP + max (f32x2, 10-nb blocking) ----------------
// smem: W1[128][64] + W2[64][64] + xi[8][64] + dup[8][KB][64] f32x2 + 4*64 params
#define EC_SMEM ((128 * 64 + 64 * 64 + 8 * 64 + 8 * KB * 64 * 2 + 4 * 64) * 4)

__global__ void __launch_bounds__(256, 2)
edgeconv_kernel(const float* __restrict__ x, const int* __restrict__ mask,
                const float* __restrict__ W1, const float* __restrict__ b1,
                const float* __restrict__ gamma, const float* __restrict__ beta,
                const float* __restrict__ W2, const float* __restrict__ b2,
                float* __restrict__ out) {
    extern __shared__ float sm[];
    float* W1s = sm;                             // 128*64
    float* W2s = W1s + 128 * 64;                 // 64*64
    float* xi_s = W2s + 64 * 64;                 // 8*64
    float* dup  = xi_s + 8 * 64;                 // 8 warps * KB * 64 f32x2
    float* b1s = dup + 8 * KB * 64 * 2;          // 64
    float* b2s = b1s + 64;
    float* gms = b2s + 64;
    float* bts = gms + 64;

    const int w = threadIdx.x >> 5;
    const int lane = threadIdx.x & 31;
    const int b = blockIdx.y;
    const int i0 = blockIdx.x * 8;
    const int i = i0 + w;
    const int c0 = 2 * lane;

    for (int e = threadIdx.x; e < 128 * 64; e += 256) W1s[e] = W1[e];
    for (int e = threadIdx.x; e < 64 * 64; e += 256) W2s[e] = W2[e];
    for (int e = threadIdx.x; e < 8 * 64; e += 256)
        xi_s[e] = x[((size_t)b * NN + i0) * DD + e];
    if (threadIdx.x < 64) {
        int t = threadIdx.x;
        b1s[t] = b1[t]; b2s[t] = b2[t]; gms[t] = gamma[t]; bts[t] = beta[t];
    }
    __syncthreads();

    const bool maski = mask[b * NN + i] != 0;
    float* orow = out + ((size_t)(b * NN + i)) * CC;
    if (!maski) {
        *(float2*)(orow + c0) = make_float2(0.f, 0.f);
        return;   // no block-wide barriers below (warp-local sync only)
    }

    // hoisted per-lane channel params (packed)
    const float2 gmv = *(const float2*)(gms + c0);
    const float2 btv = *(const float2*)(bts + c0);
    const u64 b2p = *(const u64*)(b2s + c0);

    // base = b1 + x_i @ W1[:64]  (identical for all k neighbors), packed {c0,c0+1}
    u64 basep = *(const u64*)(b1s + c0);
#pragma unroll 8
    for (int d = 0; d < DD; d++) {
        float e = xi_s[w * DD + d];
        u64 wv = *(const u64*)(W1s + d * CC + c0);
        basep = fma2(pack2(e, e), wv, basep);
    }

    float m0 = -F_INF, m1 = -F_INF;
    const int* idxrow = g_idx + ((size_t)(b * NN + i)) * KMAX;
    float* mydup = dup + w * KB * 64 * 2;            // KB neighbors x 64 f32x2
    const u64* mydupU = (const u64*)mydup;

    for (int kb = 0; kb < KMAX; kb += KB) {
        int jn[KB];
#pragma unroll
        for (int u = 0; u < KB; u++) jn[u] = idxrow[kb + u];

        // stage (x_nb - x_i), duplicated for f32x2 broadcast
#pragma unroll
        for (int u = 0; u < KB; u++) {
            const float* xr = x + ((size_t)b * NN + jn[u]) * DD;
            float e0 = xr[lane]      - xi_s[w * DD + lane];
            float e1 = xr[lane + 32] - xi_s[w * DD + lane + 32];
            ((float2*)mydup)[u * 64 + lane]      = make_float2(e0, e0);
            ((float2*)mydup)[u * 64 + lane + 32] = make_float2(e1, e1);
        }
        __syncwarp();

        u64 a[KB];
#pragma unroll
        for (int u = 0; u < KB; u++) a[u] = basep;

#pragma unroll 4
        for (int d = 0; d < DD; d++) {
            u64 wv = *(const u64*)(W1s + (DD + d) * CC + c0);
#pragma unroll
            for (int u = 0; u < KB; u++)
                a[u] = fma2(mydupU[u * 64 + d], wv, a[u]);
        }
        __syncwarp();  // dup reads done; buffer reused for h

        // GroupNorm(16 groups of 4 ch) + relu. Lane owns ch {2L,2L+1};
        // partner lane L^1 owns the other half of the 4-ch group.
#pragma unroll
        for (int u = 0; u < KB; u++) {
            float v0, v1; unpack2(a[u], v0, v1);
            float s = v0 + v1;
            s += __shfl_xor_sync(0xffffffffu, s, 1);
            float mu = s * 0.25f;
            float dv0 = v0 - mu, dv1 = v1 - mu;
            float q = dv0 * dv0 + dv1 * dv1;
            q += __shfl_xor_sync(0xffffffffu, q, 1);
            float rs = rsqrtf(q * 0.25f + 1e-5f);
            float h0 = fmaxf(dv0 * rs * gmv.x + btv.x, 0.f);
            float h1 = fmaxf(dv1 * rs * gmv.y + btv.y, 0.f);
            // duplicated store: dup[u][c0]={h0,h0}, dup[u][c0+1]={h1,h1}
            ((float4*)mydup)[(u * 64 + c0) >> 1] = make_float4(h0, h0, h1, h1);
        }
        __syncwarp();

        // h @ W2 + b2
        u64 o[KB];
#pragma unroll
        for (int u = 0; u < KB; u++) o[u] = b2p;
#pragma unroll 4
        for (int c = 0; c < CC; c++) {
            u64 wv = *(const u64*)(W2s + c * CC + c0);
#pragma unroll
            for (int u = 0; u < KB; u++)
                o[u] = fma2(mydupU[u * 64 + c], wv, o[u]);
        }
#pragma unroll
        for (int u = 0; u < KB; u++) {
            float v0, v1; unpack2(o[u], v0, v1);
            m0 = fmaxf(m0, v0);
            m1 = fmaxf(m1, v1);
        }
        __syncwarp();  // before next kb reuses dup buffer
    }

    *(float2*)(orow + c0) = make_float2(m0, m1);
}

// ---------------- launch ----------------
extern "C" void kernel_launch(void* const* d_in, const int* in_sizes, int n_in,
                              void* d_out, int out_size) {
    const float* x      = (const float*)d_in[0];
    const int*   mask   = (const int*)d_in[1];
    const float* W1     = (const float*)d_in[2];
    const float* b1     = (const float*)d_in[3];
    const float* gamma  = (const float*)d_in[4];
    const float* beta   = (const float*)d_in[5];
    const float* W2     = (const float*)d_in[6];
    const float* b2     = (const float*)d_in[7];
    float* out          = (float*)d_out;

    cudaFuncSetAttribute(knn_kernel, cudaFuncAttributeMaxDynamicSharedMemorySize, KNN_SMEM);
    cudaFuncSetAttribute(edgeconv_kernel, cudaFuncAttributeMaxDynamicSharedMemorySize, EC_SMEM);
    (void)in_sizes; (void)n_in; (void)out_size;

    prep_kernel<<<BB, 256>>>(x, mask);
    finalize_kernel<<<1, 32>>>();
    knn_kernel<<<dim3(NN / ROWS, BB), 256, KNN_SMEM>>>(x, mask);
    edgeconv_kernel<<<dim3(NN / 8, BB), 256, EC_SMEM>>>(x, mask, W1, b1, gamma, beta, W2, b2, out);
}